// round 1
// baseline (speedup 1.0000x reference)
#include <cuda_runtime.h>
#include <cstdint>

#define D256 256
#define NMAX 100000
#define EMAX 1600000
#define SCAN_BLK 1024
#define SCAN_NB ((NMAX + SCAN_BLK - 1) / SCAN_BLK)   // 98

// ---------- scratch (device globals: no allocation allowed) ----------
__device__ float g_x[(size_t)NMAX * D256];      // layer input
__device__ float g_h[(size_t)NMAX * D256];      // layer-1 output
__device__ float g_mean[(size_t)NMAX * D256];   // aggregated mean
__device__ int   g_cnt[NMAX + 1];
__device__ int   g_incl[NMAX + 1];
__device__ int   g_rowptr[NMAX + 2];
__device__ int   g_wptr[NMAX + 1];
__device__ int   g_col[EMAX];
__device__ int   g_part[256];
__device__ int   g_poff[256];

// ---------- small utility kernels ----------
__global__ void zero_cnt_kernel(int n) {
    int i = blockIdx.x * blockDim.x + threadIdx.x;
    if (i < n) g_cnt[i] = 0;
}

// x[i,:] = emb[x_idx[i],:]   (float4 granular)
__global__ void gather_x_kernel(const float* __restrict__ emb,
                                const int* __restrict__ idx,
                                float* __restrict__ xout, int N) {
    int t = blockIdx.x * blockDim.x + threadIdx.x;
    int total = N * (D256 / 4);
    if (t >= total) return;
    int r = t >> 6;          // row
    int c = t & 63;          // float4 col
    ((float4*)xout)[(size_t)r * 64 + c] =
        ((const float4*)emb)[(size_t)idx[r] * 64 + c];
}

__global__ void hist_kernel(const int* __restrict__ dst, int E) {
    int i = blockIdx.x * blockDim.x + threadIdx.x;
    if (i < E) atomicAdd(&g_cnt[dst[i]], 1);
}

__global__ void scan_local_kernel(int N) {
    __shared__ int s[SCAN_BLK];
    int i = blockIdx.x * SCAN_BLK + threadIdx.x;
    int v = (i < N) ? g_cnt[i] : 0;
    s[threadIdx.x] = v;
    __syncthreads();
    for (int off = 1; off < SCAN_BLK; off <<= 1) {
        int t = (threadIdx.x >= off) ? s[threadIdx.x - off] : 0;
        __syncthreads();
        s[threadIdx.x] += t;
        __syncthreads();
    }
    if (i < N) g_incl[i] = s[threadIdx.x];
    if (threadIdx.x == SCAN_BLK - 1) g_part[blockIdx.x] = s[SCAN_BLK - 1];
}

__global__ void scan_part_kernel(int nb) {
    int run = 0;
    for (int b = 0; b < nb; b++) { g_poff[b] = run; run += g_part[b]; }
}

__global__ void scan_final_kernel(int N) {
    int i = blockIdx.x * SCAN_BLK + threadIdx.x;
    if (i < N) {
        int v = g_incl[i] + g_poff[blockIdx.x];
        g_rowptr[i + 1] = v;
        g_wptr[i] = v - g_cnt[i];
    }
    if (i == 0) g_rowptr[0] = 0;
}

__global__ void scatter_kernel(const int* __restrict__ src,
                               const int* __restrict__ dst, int E) {
    int i = blockIdx.x * blockDim.x + threadIdx.x;
    if (i < E) {
        int pos = atomicAdd(&g_wptr[dst[i]], 1);
        g_col[pos] = src[i];
    }
}

// mean[i,:] = (1/max(deg,1)) * sum_{j in N(i)} x[col[j],:]
// one warp per node, lane owns cols lane*4 and 128+lane*4 (two float4)
__global__ void aggregate_kernel(const float* __restrict__ x,
                                 float* __restrict__ mean, int N) {
    int warp = (blockIdx.x * blockDim.x + threadIdx.x) >> 5;
    int lane = threadIdx.x & 31;
    if (warp >= N) return;
    int beg = g_rowptr[warp];
    int end = g_rowptr[warp + 1];
    float4 a0 = make_float4(0.f, 0.f, 0.f, 0.f);
    float4 a1 = make_float4(0.f, 0.f, 0.f, 0.f);
    for (int j = beg; j < end; j++) {
        int s = g_col[j];
        const float4* row = (const float4*)(x + (size_t)s * D256);
        float4 v0 = row[lane];
        float4 v1 = row[lane + 32];
        a0.x += v0.x; a0.y += v0.y; a0.z += v0.z; a0.w += v0.w;
        a1.x += v1.x; a1.y += v1.y; a1.z += v1.z; a1.w += v1.w;
    }
    int deg = end - beg;
    float sc = 1.0f / (float)(deg > 1 ? deg : 1);
    a0.x *= sc; a0.y *= sc; a0.z *= sc; a0.w *= sc;
    a1.x *= sc; a1.y *= sc; a1.z *= sc; a1.w *= sc;
    float4* mrow = (float4*)(mean + (size_t)warp * D256);
    mrow[lane]      = a0;
    mrow[lane + 32] = a1;
}

// C[M,256] = Am@Wl + Ax@Wr + bias   (logical [M,512]@[512,256])
// 128x128 tile, BK=8, 256 threads, 8x8 per thread
__global__ void __launch_bounds__(256)
gemm_kernel(const float* __restrict__ Am, const float* __restrict__ Ax,
            const float* __restrict__ Wl, const float* __restrict__ Wr,
            const float* __restrict__ bias, float* __restrict__ C, int M) {
    __shared__ float As[8][128];
    __shared__ float Bs[8][128];

    int t = threadIdx.x;
    int bm = blockIdx.y * 128;
    int bn = blockIdx.x * 128;
    int ty = t >> 4;          // 0..15, row group
    int tx = t & 15;          // 0..15, col group

    float acc[8][8];
#pragma unroll
    for (int i = 0; i < 8; i++)
#pragma unroll
        for (int j = 0; j < 8; j++) acc[i][j] = 0.f;

    int ar  = t >> 1;          // A tile row 0..127
    int ac4 = (t & 1) * 4;     // A tile col group (0 or 4)
    int br  = t >> 5;          // B tile row 0..7
    int bc4 = (t & 31) * 4;    // B tile col group
    int arow = bm + ar;
    if (arow > M - 1) arow = M - 1;   // clamp; stores guarded

    for (int k0 = 0; k0 < 512; k0 += 8) {
        const float* A = (k0 < 256) ? Am : Ax;
        const float* W = (k0 < 256) ? Wl : Wr;
        int kl = k0 & 255;
        float4 av = *(const float4*)&A[(size_t)arow * 256 + kl + ac4];
        float4 bv = *(const float4*)&W[(size_t)(kl + br) * 256 + bn + bc4];
        __syncthreads();
        As[ac4 + 0][ar] = av.x;
        As[ac4 + 1][ar] = av.y;
        As[ac4 + 2][ar] = av.z;
        As[ac4 + 3][ar] = av.w;
        *(float4*)&Bs[br][bc4] = bv;
        __syncthreads();
#pragma unroll
        for (int kk = 0; kk < 8; kk++) {
            float a[8], b[8];
            *(float4*)&a[0] = *(const float4*)&As[kk][ty * 8];
            *(float4*)&a[4] = *(const float4*)&As[kk][ty * 8 + 4];
            *(float4*)&b[0] = *(const float4*)&Bs[kk][tx * 8];
            *(float4*)&b[4] = *(const float4*)&Bs[kk][tx * 8 + 4];
#pragma unroll
            for (int i = 0; i < 8; i++)
#pragma unroll
                for (int j = 0; j < 8; j++) acc[i][j] += a[i] * b[j];
        }
    }

    float bb[8];
#pragma unroll
    for (int j = 0; j < 8; j++) bb[j] = bias[bn + tx * 8 + j];

#pragma unroll
    for (int i = 0; i < 8; i++) {
        int m = bm + ty * 8 + i;
        if (m < M) {
            float4 v0, v1;
            v0.x = acc[i][0] + bb[0]; v0.y = acc[i][1] + bb[1];
            v0.z = acc[i][2] + bb[2]; v0.w = acc[i][3] + bb[3];
            v1.x = acc[i][4] + bb[4]; v1.y = acc[i][5] + bb[5];
            v1.z = acc[i][6] + bb[6]; v1.w = acc[i][7] + bb[7];
            *(float4*)&C[(size_t)m * 256 + bn + tx * 8]     = v0;
            *(float4*)&C[(size_t)m * 256 + bn + tx * 8 + 4] = v1;
        }
    }
}

// drug/se gathers from the final x (which already lives in d_out tail)
__global__ void gather_out_kernel(const float* __restrict__ xf,
                                  const int* __restrict__ idxA, int nA,
                                  const int* __restrict__ idxB,
                                  float* __restrict__ out) {
    int r = blockIdx.x;
    int srow = (r < nA) ? idxA[r] : idxB[r - nA];
    ((float4*)(out + (size_t)r * D256))[threadIdx.x] =
        ((const float4*)(xf + (size_t)srow * D256))[threadIdx.x];
}

extern "C" void kernel_launch(void* const* d_in, const int* in_sizes, int n_in,
                              void* d_out, int out_size) {
    const float* emb = (const float*)d_in[0];
    const float* W1l = (const float*)d_in[1];
    const float* b1l = (const float*)d_in[2];
    const float* W1r = (const float*)d_in[3];
    const float* W2l = (const float*)d_in[4];
    const float* b2l = (const float*)d_in[5];
    const float* W2r = (const float*)d_in[6];
    const int* x_idx = (const int*)d_in[7];
    const int* edge  = (const int*)d_in[8];
    const int* drug  = (const int*)d_in[9];
    const int* se    = (const int*)d_in[10];

    int N = in_sizes[7];
    int E = in_sizes[8] / 2;
    const int* src = edge;
    const int* dst = edge + E;
    int nd = in_sizes[9];
    int ns = in_sizes[10];

    float* out   = (float*)d_out;
    float* out_x = out + (size_t)(nd + ns) * D256;   // final x lives here

    float *px, *ph, *pm;
    cudaGetSymbolAddress((void**)&px, g_x);
    cudaGetSymbolAddress((void**)&ph, g_h);
    cudaGetSymbolAddress((void**)&pm, g_mean);

    int nb = (N + SCAN_BLK - 1) / SCAN_BLK;

    // --- build inputs + CSR (once; shared by both layers) ---
    zero_cnt_kernel<<<(N + 255) / 256, 256>>>(N);
    gather_x_kernel<<<(N * 64 + 255) / 256, 256>>>(emb, x_idx, px, N);
    hist_kernel<<<(E + 255) / 256, 256>>>(dst, E);
    scan_local_kernel<<<nb, SCAN_BLK>>>(N);
    scan_part_kernel<<<1, 1>>>(nb);
    scan_final_kernel<<<nb, SCAN_BLK>>>(N);
    scatter_kernel<<<(E + 255) / 256, 256>>>(src, dst, E);

    dim3 ggrid(2, (N + 127) / 128);

    // --- layer 1 ---
    aggregate_kernel<<<(N * 32 + 255) / 256, 256>>>(px, pm, N);
    gemm_kernel<<<ggrid, 256>>>(pm, px, W1l, W1r, b1l, ph, N);

    // --- layer 2 (writes final x straight into d_out) ---
    aggregate_kernel<<<(N * 32 + 255) / 256, 256>>>(ph, pm, N);
    gemm_kernel<<<ggrid, 256>>>(pm, ph, W2l, W2r, b2l, out_x, N);

    // --- drug / se gathers ---
    gather_out_kernel<<<nd + ns, 64>>>(out_x, drug, nd, se, out);
}

// round 3
// speedup vs baseline: 1.8601x; 1.8601x over previous
#include <cuda_runtime.h>
#include <cuda_bf16.h>
#include <cstdint>

#define D256 256
#define NMAX 100000
#define EMAX 1600000
#define SCAN_BLK 1024

// ---------------- scratch (device globals) ----------------
__device__ float g_x[(size_t)NMAX * D256];
__device__ float g_h[(size_t)NMAX * D256];
__device__ float g_mean[(size_t)NMAX * D256];
__device__ int   g_cnt[NMAX + 1];
__device__ int   g_incl[NMAX + 1];
__device__ int   g_rowptr[NMAX + 2];
__device__ int   g_wptr[NMAX + 1];
__device__ int   g_col[EMAX];
__device__ int   g_part[256];
__device__ int   g_poff[256];
// pre-converted weights: [layer][n (256)][k (512)] bf16 hi/lo (B^T layout for row.col mma)
__device__ __nv_bfloat16 g_Bhi[2 * 256 * 512];
__device__ __nv_bfloat16 g_Blo[2 * 256 * 512];

// ---------------- helpers ----------------
__device__ __forceinline__ float bf_hi(float v) {
    return __bfloat162float(__float2bfloat16_rn(v));
}
__device__ __forceinline__ uint32_t pk(float a, float b) {
    uint32_t lo = __bfloat16_as_ushort(__float2bfloat16_rn(a));
    uint32_t hi = __bfloat16_as_ushort(__float2bfloat16_rn(b));
    return lo | (hi << 16);
}
__device__ __forceinline__ void mma_bf16(float* c, const uint32_t* a, const uint32_t* b) {
    asm volatile(
        "mma.sync.aligned.m16n8k16.row.col.f32.bf16.bf16.f32 "
        "{%0,%1,%2,%3}, {%4,%5,%6,%7}, {%8,%9}, {%0,%1,%2,%3};"
        : "+f"(c[0]), "+f"(c[1]), "+f"(c[2]), "+f"(c[3])
        : "r"(a[0]), "r"(a[1]), "r"(a[2]), "r"(a[3]), "r"(b[0]), "r"(b[1]));
}

// ---------------- small utility kernels ----------------
__global__ void zero_cnt_kernel(int n) {
    int i = blockIdx.x * blockDim.x + threadIdx.x;
    if (i < n) g_cnt[i] = 0;
}
__global__ void gather_x_kernel(const float* __restrict__ emb,
                                const int* __restrict__ idx,
                                float* __restrict__ xout, int N) {
    int t = blockIdx.x * blockDim.x + threadIdx.x;
    if (t >= N * 64) return;
    int r = t >> 6, c = t & 63;
    ((float4*)xout)[(size_t)r * 64 + c] = ((const float4*)emb)[(size_t)idx[r] * 64 + c];
}
__global__ void hist_kernel(const int* __restrict__ dst, int E) {
    int i = blockIdx.x * blockDim.x + threadIdx.x;
    if (i < E) atomicAdd(&g_cnt[dst[i]], 1);
}
__global__ void scan_local_kernel(int N) {
    __shared__ int s[SCAN_BLK];
    int i = blockIdx.x * SCAN_BLK + threadIdx.x;
    int v = (i < N) ? g_cnt[i] : 0;
    s[threadIdx.x] = v;
    __syncthreads();
    for (int off = 1; off < SCAN_BLK; off <<= 1) {
        int t = (threadIdx.x >= off) ? s[threadIdx.x - off] : 0;
        __syncthreads();
        s[threadIdx.x] += t;
        __syncthreads();
    }
    if (i < N) g_incl[i] = s[threadIdx.x];
    if (threadIdx.x == SCAN_BLK - 1) g_part[blockIdx.x] = s[SCAN_BLK - 1];
}
__global__ void scan_part_kernel(int nb) {
    int run = 0;
    for (int b = 0; b < nb; b++) { g_poff[b] = run; run += g_part[b]; }
}
__global__ void scan_final_kernel(int N) {
    int i = blockIdx.x * SCAN_BLK + threadIdx.x;
    if (i < N) {
        int v = g_incl[i] + g_poff[blockIdx.x];
        g_rowptr[i + 1] = v;
        g_wptr[i] = v - g_cnt[i];
    }
    if (i == 0) g_rowptr[0] = 0;
}
__global__ void scatter_kernel(const int* __restrict__ src,
                               const int* __restrict__ dst, int E) {
    int i = blockIdx.x * blockDim.x + threadIdx.x;
    if (i < E) {
        int pos = atomicAdd(&g_wptr[dst[i]], 1);
        g_col[pos] = src[i];
    }
}
__global__ void aggregate_kernel(const float* __restrict__ x,
                                 float* __restrict__ mean, int N) {
    int warp = (blockIdx.x * blockDim.x + threadIdx.x) >> 5;
    int lane = threadIdx.x & 31;
    if (warp >= N) return;
    int beg = g_rowptr[warp], end = g_rowptr[warp + 1];
    float4 a0 = make_float4(0.f, 0.f, 0.f, 0.f);
    float4 a1 = make_float4(0.f, 0.f, 0.f, 0.f);
    for (int j = beg; j < end; j++) {
        const float4* row = (const float4*)(x + (size_t)g_col[j] * D256);
        float4 v0 = row[lane], v1 = row[lane + 32];
        a0.x += v0.x; a0.y += v0.y; a0.z += v0.z; a0.w += v0.w;
        a1.x += v1.x; a1.y += v1.y; a1.z += v1.z; a1.w += v1.w;
    }
    int deg = end - beg;
    float sc = 1.0f / (float)(deg > 1 ? deg : 1);
    a0.x *= sc; a0.y *= sc; a0.z *= sc; a0.w *= sc;
    a1.x *= sc; a1.y *= sc; a1.z *= sc; a1.w *= sc;
    float4* m = (float4*)(mean + (size_t)warp * D256);
    m[lane] = a0; m[lane + 32] = a1;
}

// convert W (fp32, [k][n]) -> g_B (bf16 hi/lo, [layer][n][k]) once
__global__ void convW_kernel(const float* __restrict__ W1l, const float* __restrict__ W1r,
                             const float* __restrict__ W2l, const float* __restrict__ W2r) {
    int t = blockIdx.x * blockDim.x + threadIdx.x;
    if (t >= 2 * 256 * 512) return;
    int layer = t >> 17;
    int rem = t & 131071;
    int n = rem >> 9;
    int k = rem & 511;
    const float* Wl = layer ? W2l : W1l;
    const float* Wr = layer ? W2r : W1r;
    float v = (k < 256) ? Wl[k * 256 + n] : Wr[(k - 256) * 256 + n];
    __nv_bfloat16 h = __float2bfloat16_rn(v);
    g_Bhi[t] = h;
    g_Blo[t] = __float2bfloat16_rn(v - __bfloat162float(h));
}

// ---------------- mma.sync GEMM ----------------
// C[M,256] = Am@Wl + Ax@Wr + bias, split-bf16 3-term.
// CTA 256 thr (8 warps): tile M=128 x N=128.  Warp tile 32x64 (wm=wid>>1, wn=wid&1).
// K loop: 16 chunks of 32 (first 8 from Am, last 8 from Ax; B pre-concat [n][512]).
#define ASTRIDE 40   // bf16 elems per row (32 + 8 pad) -> 80B
__global__ void __launch_bounds__(256, 2)
gemm_mma_kernel(const float* __restrict__ Am, const float* __restrict__ Ax,
                const __nv_bfloat16* __restrict__ Bhi, const __nv_bfloat16* __restrict__ Blo,
                const float* __restrict__ bias, float* __restrict__ C, int M) {
    __shared__ __nv_bfloat16 Ashi[128 * ASTRIDE];
    __shared__ __nv_bfloat16 Aslo[128 * ASTRIDE];
    __shared__ __nv_bfloat16 Bshi[128 * ASTRIDE];
    __shared__ __nv_bfloat16 Bslo[128 * ASTRIDE];
    __shared__ float sbias[128];

    int tid = threadIdx.x;
    int wid = tid >> 5, lane = tid & 31;
    int wm = wid >> 1, wn = wid & 1;
    int qr = lane >> 2;          // 0..7
    int qc = (lane & 3) * 2;     // 0,2,4,6
    int bm = blockIdx.y * 128;
    int bn = blockIdx.x * 128;

    if (tid < 128) sbias[tid] = bias[bn + tid];

    float acc[2][8][4];
#pragma unroll
    for (int i = 0; i < 2; i++)
#pragma unroll
        for (int j = 0; j < 8; j++)
#pragma unroll
            for (int v = 0; v < 4; v++) acc[i][j][v] = 0.f;

    for (int c = 0; c < 16; c++) {
        const float* A = (c < 8) ? Am : Ax;
        int kl = (c & 7) * 32;
        int k0 = c * 32;
        __syncthreads();
        // --- A: 128 rows x 32 floats -> bf16 hi/lo, 512 slots of 8 floats ---
#pragma unroll
        for (int it = 0; it < 2; it++) {
            int item = it * 256 + tid;
            int r = item >> 2, kg = item & 3;
            int arow = bm + r; if (arow >= M) arow = M - 1;
            const float4* p = (const float4*)(A + (size_t)arow * 256 + kl + kg * 8);
            float4 v0 = p[0], v1 = p[1];
            float h0 = bf_hi(v0.x), h1 = bf_hi(v0.y), h2 = bf_hi(v0.z), h3 = bf_hi(v0.w);
            float h4 = bf_hi(v1.x), h5 = bf_hi(v1.y), h6 = bf_hi(v1.z), h7 = bf_hi(v1.w);
            uint32_t off = r * ASTRIDE + kg * 8;    // bf16 elements
            *(uint4*)&Ashi[off] = make_uint4(pk(h0, h1), pk(h2, h3), pk(h4, h5), pk(h6, h7));
            *(uint4*)&Aslo[off] = make_uint4(
                pk(v0.x - h0, v0.y - h1), pk(v0.z - h2, v0.w - h3),
                pk(v1.x - h4, v1.y - h5), pk(v1.z - h6, v1.w - h7));
        }
        // --- B: 128 n-rows x 32 bf16, hi+lo, 1024 slots of 8 bf16 ---
#pragma unroll
        for (int it = 0; it < 4; it++) {
            int item = it * 256 + tid;
            int mat = item >> 9;
            int rem = item & 511;
            int n = rem >> 2, kg = rem & 3;
            const __nv_bfloat16* src = (mat ? Blo : Bhi) + (size_t)(bn + n) * 512 + k0 + kg * 8;
            uint4 v = *(const uint4*)src;
            uint32_t off = n * ASTRIDE + kg * 8;
            if (mat) *(uint4*)&Bslo[off] = v;
            else     *(uint4*)&Bshi[off] = v;
        }
        __syncthreads();

        // --- compute: 2 k16-steps ---
#pragma unroll
        for (int k16 = 0; k16 < 32; k16 += 16) {
            uint32_t ahi[2][4], alo[2][4];
#pragma unroll
            for (int mt = 0; mt < 2; mt++) {
                int r0 = wm * 32 + mt * 16 + qr;
                uint32_t o00 = r0 * ASTRIDE + k16 + qc;
                uint32_t o10 = (r0 + 8) * ASTRIDE + k16 + qc;
                ahi[mt][0] = *(const uint32_t*)&Ashi[o00];
                ahi[mt][1] = *(const uint32_t*)&Ashi[o10];
                ahi[mt][2] = *(const uint32_t*)&Ashi[o00 + 8];
                ahi[mt][3] = *(const uint32_t*)&Ashi[o10 + 8];
                alo[mt][0] = *(const uint32_t*)&Aslo[o00];
                alo[mt][1] = *(const uint32_t*)&Aslo[o10];
                alo[mt][2] = *(const uint32_t*)&Aslo[o00 + 8];
                alo[mt][3] = *(const uint32_t*)&Aslo[o10 + 8];
            }
#pragma unroll
            for (int nt = 0; nt < 8; nt++) {
                int n0 = wn * 64 + nt * 8 + qr;
                uint32_t ob = n0 * ASTRIDE + k16 + qc;
                uint32_t bhi[2], blo[2];
                bhi[0] = *(const uint32_t*)&Bshi[ob];
                bhi[1] = *(const uint32_t*)&Bshi[ob + 8];
                blo[0] = *(const uint32_t*)&Bslo[ob];
                blo[1] = *(const uint32_t*)&Bslo[ob + 8];
#pragma unroll
                for (int mt = 0; mt < 2; mt++) {
                    mma_bf16(acc[mt][nt], ahi[mt], bhi);
                    mma_bf16(acc[mt][nt], ahi[mt], blo);
                    mma_bf16(acc[mt][nt], alo[mt], bhi);
                }
            }
        }
    }

    // --- epilogue ---
#pragma unroll
    for (int mt = 0; mt < 2; mt++) {
        int r0 = bm + wm * 32 + mt * 16 + qr;
#pragma unroll
        for (int nt = 0; nt < 8; nt++) {
            int lc = wn * 64 + nt * 8 + qc;
            int col = bn + lc;
            float b0 = sbias[lc], b1 = sbias[lc + 1];
            if (r0 < M) {
                float2 o = make_float2(acc[mt][nt][0] + b0, acc[mt][nt][1] + b1);
                *(float2*)&C[(size_t)r0 * 256 + col] = o;
            }
            if (r0 + 8 < M) {
                float2 o = make_float2(acc[mt][nt][2] + b0, acc[mt][nt][3] + b1);
                *(float2*)&C[(size_t)(r0 + 8) * 256 + col] = o;
            }
        }
    }
}

__global__ void gather_out_kernel(const float* __restrict__ xf,
                                  const int* __restrict__ idxA, int nA,
                                  const int* __restrict__ idxB,
                                  float* __restrict__ out) {
    int r = blockIdx.x;
    int srow = (r < nA) ? idxA[r] : idxB[r - nA];
    ((float4*)(out + (size_t)r * D256))[threadIdx.x] =
        ((const float4*)(xf + (size_t)srow * D256))[threadIdx.x];
}

extern "C" void kernel_launch(void* const* d_in, const int* in_sizes, int n_in,
                              void* d_out, int out_size) {
    const float* emb = (const float*)d_in[0];
    const float* W1l = (const float*)d_in[1];
    const float* b1l = (const float*)d_in[2];
    const float* W1r = (const float*)d_in[3];
    const float* W2l = (const float*)d_in[4];
    const float* b2l = (const float*)d_in[5];
    const float* W2r = (const float*)d_in[6];
    const int* x_idx = (const int*)d_in[7];
    const int* edge  = (const int*)d_in[8];
    const int* drug  = (const int*)d_in[9];
    const int* se    = (const int*)d_in[10];

    int N = in_sizes[7];
    int E = in_sizes[8] / 2;
    const int* src = edge;
    const int* dst = edge + E;
    int nd = in_sizes[9];
    int ns = in_sizes[10];

    float* out   = (float*)d_out;
    float* out_x = out + (size_t)(nd + ns) * D256;

    float *px, *ph, *pm;
    __nv_bfloat16 *pbh, *pbl;
    cudaGetSymbolAddress((void**)&px, g_x);
    cudaGetSymbolAddress((void**)&ph, g_h);
    cudaGetSymbolAddress((void**)&pm, g_mean);
    cudaGetSymbolAddress((void**)&pbh, g_Bhi);
    cudaGetSymbolAddress((void**)&pbl, g_Blo);

    int nb = (N + SCAN_BLK - 1) / SCAN_BLK;

    // --- CSR build + input gather + weight conversion ---
    zero_cnt_kernel<<<(N + 255) / 256, 256>>>(N);
    gather_x_kernel<<<(N * 64 + 255) / 256, 256>>>(emb, x_idx, px, N);
    convW_kernel<<<(2 * 256 * 512 + 255) / 256, 256>>>(W1l, W1r, W2l, W2r);
    hist_kernel<<<(E + 255) / 256, 256>>>(dst, E);
    scan_local_kernel<<<nb, SCAN_BLK>>>(N);
    scan_part_kernel<<<1, 1>>>(nb);
    scan_final_kernel<<<nb, SCAN_BLK>>>(N);
    scatter_kernel<<<(E + 255) / 256, 256>>>(src, dst, E);

    dim3 ggrid(2, (N + 127) / 128);

    // --- layer 1 ---
    aggregate_kernel<<<(N * 32 + 255) / 256, 256>>>(px, pm, N);
    gemm_mma_kernel<<<ggrid, 256>>>(pm, px, pbh, pbl, b1l, ph, N);

    // --- layer 2 ---
    aggregate_kernel<<<(N * 32 + 255) / 256, 256>>>(ph, pm, N);
    gemm_mma_kernel<<<ggrid, 256>>>(pm, ph, pbh + 256 * 512, pbl + 256 * 512,
                                    b2l, out_x, N);

    // --- output gathers ---
    gather_out_kernel<<<nd + ns, 64>>>(out_x, drug, nd, se, out);
}

// round 4
// speedup vs baseline: 2.0632x; 1.1092x over previous
#include <cuda_runtime.h>
#include <cuda_bf16.h>
#include <cstdint>

#define D256 256
#define NMAX 100000
#define EMAX 1600000
#define SCAN_BLK 1024

// ---------------- scratch (device globals) ----------------
__device__ float g_x[(size_t)NMAX * D256];      // fp32 x (for aggregation)
__device__ float g_h[(size_t)NMAX * D256];      // fp32 h (for layer-2 aggregation)
__device__ __nv_bfloat16 g_xhi[(size_t)NMAX * D256];
__device__ __nv_bfloat16 g_xlo[(size_t)NMAX * D256];
__device__ __nv_bfloat16 g_hhi[(size_t)NMAX * D256];
__device__ __nv_bfloat16 g_hlo[(size_t)NMAX * D256];
__device__ __nv_bfloat16 g_mhi[(size_t)NMAX * D256];
__device__ __nv_bfloat16 g_mlo[(size_t)NMAX * D256];
__device__ int   g_cnt[NMAX + 1];
__device__ int   g_incl[NMAX + 1];
__device__ int   g_rowptr[NMAX + 2];
__device__ int   g_wptr[NMAX + 1];
__device__ int   g_col[EMAX];
__device__ int   g_part[256];
__device__ int   g_poff[256];
// pre-converted weights: [layer][n (256)][k (512)] bf16 hi/lo
__device__ __nv_bfloat16 g_Bhi[2 * 256 * 512];
__device__ __nv_bfloat16 g_Blo[2 * 256 * 512];

// ---------------- helpers ----------------
__device__ __forceinline__ float bf_hi(float v) {
    return __bfloat162float(__float2bfloat16_rn(v));
}
__device__ __forceinline__ uint32_t pk(float a, float b) {
    uint32_t lo = __bfloat16_as_ushort(__float2bfloat16_rn(a));
    uint32_t hi = __bfloat16_as_ushort(__float2bfloat16_rn(b));
    return lo | (hi << 16);
}
__device__ __forceinline__ uint32_t smem_u32(const void* p) {
    uint32_t a;
    asm("{ .reg .u64 t; cvta.to.shared.u64 t, %1; cvt.u32.u64 %0, t; }"
        : "=r"(a) : "l"(p));
    return a;
}
__device__ __forceinline__ void mma_bf16(float* c, const uint32_t* a, const uint32_t* b) {
    asm volatile(
        "mma.sync.aligned.m16n8k16.row.col.f32.bf16.bf16.f32 "
        "{%0,%1,%2,%3}, {%4,%5,%6,%7}, {%8,%9}, {%0,%1,%2,%3};"
        : "+f"(c[0]), "+f"(c[1]), "+f"(c[2]), "+f"(c[3])
        : "r"(a[0]), "r"(a[1]), "r"(a[2]), "r"(a[3]), "r"(b[0]), "r"(b[1]));
}
__device__ __forceinline__ void ldsm_x4(uint32_t* r, uint32_t addr) {
    asm volatile("ldmatrix.sync.aligned.m8n8.x4.shared.b16 {%0,%1,%2,%3}, [%4];"
                 : "=r"(r[0]), "=r"(r[1]), "=r"(r[2]), "=r"(r[3]) : "r"(addr));
}
#define CP_ASYNC16(dst, src) asm volatile( \
    "cp.async.cg.shared.global [%0], [%1], 16;" :: "r"(dst), "l"(src) : "memory")
#define CP_COMMIT() asm volatile("cp.async.commit_group;" ::: "memory")

// ---------------- small utility kernels ----------------
__global__ void zero_cnt_kernel(int n) {
    int i = blockIdx.x * blockDim.x + threadIdx.x;
    if (i < n) g_cnt[i] = 0;
}
// x = emb[x_idx]; writes fp32 + hi/lo bf16
__global__ void gather_x_kernel(const float* __restrict__ emb,
                                const int* __restrict__ idx, int N) {
    int t = blockIdx.x * blockDim.x + threadIdx.x;
    if (t >= N * 32) return;
    int r = t >> 5, c = t & 31;          // c: group of 8 elements
    const float4* p = (const float4*)emb + (size_t)idx[r] * 64 + c * 2;
    float4 v0 = p[0], v1 = p[1];
    size_t eo = (size_t)r * 64 + c * 2;  // float4 units
    ((float4*)g_x)[eo] = v0;
    ((float4*)g_x)[eo + 1] = v1;
    float h0 = bf_hi(v0.x), h1 = bf_hi(v0.y), h2 = bf_hi(v0.z), h3 = bf_hi(v0.w);
    float h4 = bf_hi(v1.x), h5 = bf_hi(v1.y), h6 = bf_hi(v1.z), h7 = bf_hi(v1.w);
    size_t uo = (size_t)r * 64 + c * 2;  // uint4 = 8 bf16
    ((uint4*)g_xhi)[(size_t)r * 32 + c] =
        make_uint4(pk(h0, h1), pk(h2, h3), pk(h4, h5), pk(h6, h7));
    ((uint4*)g_xlo)[(size_t)r * 32 + c] =
        make_uint4(pk(v0.x - h0, v0.y - h1), pk(v0.z - h2, v0.w - h3),
                   pk(v1.x - h4, v1.y - h5), pk(v1.z - h6, v1.w - h7));
    (void)uo;
}
__global__ void hist_kernel(const int* __restrict__ dst, int E) {
    int i = blockIdx.x * blockDim.x + threadIdx.x;
    if (i < E) atomicAdd(&g_cnt[dst[i]], 1);
}
__global__ void scan_local_kernel(int N) {
    __shared__ int s[SCAN_BLK];
    int i = blockIdx.x * SCAN_BLK + threadIdx.x;
    int v = (i < N) ? g_cnt[i] : 0;
    s[threadIdx.x] = v;
    __syncthreads();
    for (int off = 1; off < SCAN_BLK; off <<= 1) {
        int t = (threadIdx.x >= off) ? s[threadIdx.x - off] : 0;
        __syncthreads();
        s[threadIdx.x] += t;
        __syncthreads();
    }
    if (i < N) g_incl[i] = s[threadIdx.x];
    if (threadIdx.x == SCAN_BLK - 1) g_part[blockIdx.x] = s[SCAN_BLK - 1];
}
__global__ void scan_part_kernel(int nb) {
    int run = 0;
    for (int b = 0; b < nb; b++) { g_poff[b] = run; run += g_part[b]; }
}
__global__ void scan_final_kernel(int N) {
    int i = blockIdx.x * SCAN_BLK + threadIdx.x;
    if (i < N) {
        int v = g_incl[i] + g_poff[blockIdx.x];
        g_rowptr[i + 1] = v;
        g_wptr[i] = v - g_cnt[i];
    }
    if (i == 0) g_rowptr[0] = 0;
}
__global__ void scatter_kernel(const int* __restrict__ src,
                               const int* __restrict__ dst, int E) {
    int i = blockIdx.x * blockDim.x + threadIdx.x;
    if (i < E) {
        int pos = atomicAdd(&g_wptr[dst[i]], 1);
        g_col[pos] = src[i];
    }
}
// mean aggregation: reads fp32 x, writes bf16 hi/lo mean (GEMM is sole consumer)
__global__ void aggregate_kernel(const float* __restrict__ x, int N) {
    int warp = (blockIdx.x * blockDim.x + threadIdx.x) >> 5;
    int lane = threadIdx.x & 31;
    if (warp >= N) return;
    int beg = g_rowptr[warp], end = g_rowptr[warp + 1];
    float4 a0 = make_float4(0.f, 0.f, 0.f, 0.f);
    float4 a1 = make_float4(0.f, 0.f, 0.f, 0.f);
    for (int j = beg; j < end; j++) {
        const float4* row = (const float4*)(x + (size_t)g_col[j] * D256);
        float4 v0 = row[lane], v1 = row[lane + 32];
        a0.x += v0.x; a0.y += v0.y; a0.z += v0.z; a0.w += v0.w;
        a1.x += v1.x; a1.y += v1.y; a1.z += v1.z; a1.w += v1.w;
    }
    int deg = end - beg;
    float sc = 1.0f / (float)(deg > 1 ? deg : 1);
    a0.x *= sc; a0.y *= sc; a0.z *= sc; a0.w *= sc;
    a1.x *= sc; a1.y *= sc; a1.z *= sc; a1.w *= sc;
    float h0 = bf_hi(a0.x), h1 = bf_hi(a0.y), h2 = bf_hi(a0.z), h3 = bf_hi(a0.w);
    float h4 = bf_hi(a1.x), h5 = bf_hi(a1.y), h6 = bf_hi(a1.z), h7 = bf_hi(a1.w);
    // a0 -> cols lane*4..+3 ; a1 -> cols 128+lane*4..+3
    uint2* mh = (uint2*)g_mhi + (size_t)warp * 64;
    uint2* ml = (uint2*)g_mlo + (size_t)warp * 64;
    mh[lane]      = make_uint2(pk(h0, h1), pk(h2, h3));
    mh[lane + 32] = make_uint2(pk(h4, h5), pk(h6, h7));
    ml[lane]      = make_uint2(pk(a0.x - h0, a0.y - h1), pk(a0.z - h2, a0.w - h3));
    ml[lane + 32] = make_uint2(pk(a1.x - h4, a1.y - h5), pk(a1.z - h6, a1.w - h7));
}
// convert W (fp32, [k][n]) -> g_B (bf16 hi/lo, [layer][n][k]) once
__global__ void convW_kernel(const float* __restrict__ W1l, const float* __restrict__ W1r,
                             const float* __restrict__ W2l, const float* __restrict__ W2r) {
    int t = blockIdx.x * blockDim.x + threadIdx.x;
    if (t >= 2 * 256 * 512) return;
    int layer = t >> 17;
    int rem = t & 131071;
    int n = rem >> 9;
    int k = rem & 511;
    const float* Wl = layer ? W2l : W1l;
    const float* Wr = layer ? W2r : W1r;
    float v = (k < 256) ? Wl[k * 256 + n] : Wr[(k - 256) * 256 + n];
    __nv_bfloat16 h = __float2bfloat16_rn(v);
    g_Bhi[t] = h;
    g_Blo[t] = __float2bfloat16_rn(v - __bfloat162float(h));
}

// ---------------- pipelined mma.sync GEMM ----------------
// C[M,256] = Am@Wl + Ax@Wr + bias, split-bf16 3-term; A pre-split hi/lo bf16.
// CTA 256 thr, tile 128x128; warp tile 32x64. K: 16 chunks of 32 (8 Am, 8 Ax).
// 2-stage cp.async pipeline; ldmatrix fragment loads.
// smem per stage: 4 arrays x (128 rows x 80B) = 40960B; bias at 81920.
#define ROWB 80
#define STAGEB 40960
#define SM_GEMM (2 * STAGEB + 512)

__global__ void __launch_bounds__(256, 2)
gemm_mma_kernel(const __nv_bfloat16* __restrict__ Amhi, const __nv_bfloat16* __restrict__ Amlo,
                const __nv_bfloat16* __restrict__ Axhi, const __nv_bfloat16* __restrict__ Axlo,
                const __nv_bfloat16* __restrict__ Bhi, const __nv_bfloat16* __restrict__ Blo,
                const float* __restrict__ bias, float* __restrict__ Cf,
                __nv_bfloat16* __restrict__ Chi, __nv_bfloat16* __restrict__ Clo, int M) {
    extern __shared__ char smem[];
    uint32_t sb = smem_u32(smem);
    int tid = threadIdx.x;
    int wid = tid >> 5, lane = tid & 31;
    int wm = wid >> 1, wn = wid & 1;
    int qr = lane >> 2, qc = (lane & 3) * 2;
    int lr = lane & 7, lg = lane >> 3;
    int bm = blockIdx.y * 128;
    int bn = blockIdx.x * 128;

    float* sbias = (float*)(smem + 2 * STAGEB);
    if (tid < 128) sbias[tid] = bias[bn + tid];

    float acc[2][8][4];
#pragma unroll
    for (int i = 0; i < 2; i++)
#pragma unroll
        for (int j = 0; j < 8; j++)
#pragma unroll
            for (int v = 0; v < 4; v++) acc[i][j][v] = 0.f;

    // fill-chunk: 2048 x 16B transfers, 8 per thread
    auto issue_chunk = [&](int c, int stage) {
        const __nv_bfloat16* Ah = (c < 8) ? Amhi : Axhi;
        const __nv_bfloat16* Al = (c < 8) ? Amlo : Axlo;
        int kl = (c & 7) * 32;
        int k0 = c * 32;
        uint32_t sbase = sb + stage * STAGEB;
#pragma unroll
        for (int it = 0; it < 8; it++) {
            int item = it * 256 + tid;
            int arr = item >> 9, rem = item & 511, r = rem >> 2, kg = rem & 3;
            uint32_t dst = sbase + arr * 10240 + r * ROWB + kg * 16;
            const __nv_bfloat16* src;
            if (arr < 2) {
                int ar = bm + r; if (ar >= M) ar = M - 1;
                src = (arr == 0 ? Ah : Al) + (size_t)ar * 256 + kl + kg * 8;
            } else {
                src = (arr == 2 ? Bhi : Blo) + (size_t)(bn + r) * 512 + k0 + kg * 8;
            }
            CP_ASYNC16(dst, src);
        }
        CP_COMMIT();
    };

    issue_chunk(0, 0);
    for (int c = 0; c < 16; c++) {
        int st = c & 1;
        if (c < 15) {
            issue_chunk(c + 1, st ^ 1);
            asm volatile("cp.async.wait_group 1;" ::: "memory");
        } else {
            asm volatile("cp.async.wait_group 0;" ::: "memory");
        }
        __syncthreads();

        uint32_t Ahb = sb + st * STAGEB;
        uint32_t Alb = Ahb + 10240;
        uint32_t Bhb = Ahb + 20480;
        uint32_t Blb = Ahb + 30720;
        int arow0 = wm * 32 + lr + ((lg & 1) << 3);
        int brow0 = wn * 64 + lr + ((lg >> 1) << 3);
#pragma unroll
        for (int k16 = 0; k16 < 32; k16 += 16) {
            uint32_t akofs = (uint32_t)((k16 + ((lg >> 1) << 3)) * 2);
            uint32_t bkofs = (uint32_t)((k16 + ((lg & 1) << 3)) * 2);
            uint32_t ah[2][4], al[2][4];
            ldsm_x4(ah[0], Ahb + arow0 * ROWB + akofs);
            ldsm_x4(ah[1], Ahb + (arow0 + 16) * ROWB + akofs);
            ldsm_x4(al[0], Alb + arow0 * ROWB + akofs);
            ldsm_x4(al[1], Alb + (arow0 + 16) * ROWB + akofs);
#pragma unroll
            for (int p = 0; p < 4; p++) {
                uint32_t bh[4], bl[4];
                ldsm_x4(bh, Bhb + (brow0 + p * 16) * ROWB + bkofs);
                ldsm_x4(bl, Blb + (brow0 + p * 16) * ROWB + bkofs);
#pragma unroll
                for (int mt = 0; mt < 2; mt++) {
#pragma unroll
                    for (int j = 0; j < 2; j++) {
                        float* a_ = acc[mt][p * 2 + j];
                        mma_bf16(a_, ah[mt], &bh[2 * j]);
                        mma_bf16(a_, ah[mt], &bl[2 * j]);
                        mma_bf16(a_, al[mt], &bh[2 * j]);
                    }
                }
            }
        }
        __syncthreads();
    }

    // --- epilogue ---
#pragma unroll
    for (int mt = 0; mt < 2; mt++) {
        int r0 = bm + wm * 32 + mt * 16 + qr;
#pragma unroll
        for (int nt = 0; nt < 8; nt++) {
            int lc = wn * 64 + nt * 8 + qc;
            int col = bn + lc;
            float b0 = sbias[lc], b1 = sbias[lc + 1];
            float v00 = acc[mt][nt][0] + b0, v01 = acc[mt][nt][1] + b1;
            float v10 = acc[mt][nt][2] + b0, v11 = acc[mt][nt][3] + b1;
            if (Cf) {
                if (r0 < M)
                    *(float2*)&Cf[(size_t)r0 * 256 + col] = make_float2(v00, v01);
                if (r0 + 8 < M)
                    *(float2*)&Cf[(size_t)(r0 + 8) * 256 + col] = make_float2(v10, v11);
            }
            if (Chi) {
                if (r0 < M) {
                    float h0 = bf_hi(v00), h1 = bf_hi(v01);
                    ((uint32_t*)Chi)[((size_t)r0 * 256 + col) >> 1] = pk(h0, h1);
                    ((uint32_t*)Clo)[((size_t)r0 * 256 + col) >> 1] = pk(v00 - h0, v01 - h1);
                }
                if (r0 + 8 < M) {
                    float h0 = bf_hi(v10), h1 = bf_hi(v11);
                    ((uint32_t*)Chi)[((size_t)(r0 + 8) * 256 + col) >> 1] = pk(h0, h1);
                    ((uint32_t*)Clo)[((size_t)(r0 + 8) * 256 + col) >> 1] = pk(v10 - h0, v11 - h1);
                }
            }
        }
    }
}

__global__ void gather_out_kernel(const float* __restrict__ xf,
                                  const int* __restrict__ idxA, int nA,
                                  const int* __restrict__ idxB,
                                  float* __restrict__ out) {
    int r = blockIdx.x;
    int srow = (r < nA) ? idxA[r] : idxB[r - nA];
    ((float4*)(out + (size_t)r * D256))[threadIdx.x] =
        ((const float4*)(xf + (size_t)srow * D256))[threadIdx.x];
}

extern "C" void kernel_launch(void* const* d_in, const int* in_sizes, int n_in,
                              void* d_out, int out_size) {
    const float* emb = (const float*)d_in[0];
    const float* W1l = (const float*)d_in[1];
    const float* b1l = (const float*)d_in[2];
    const float* W1r = (const float*)d_in[3];
    const float* W2l = (const float*)d_in[4];
    const float* b2l = (const float*)d_in[5];
    const float* W2r = (const float*)d_in[6];
    const int* x_idx = (const int*)d_in[7];
    const int* edge  = (const int*)d_in[8];
    const int* drug  = (const int*)d_in[9];
    const int* se    = (const int*)d_in[10];

    int N = in_sizes[7];
    int E = in_sizes[8] / 2;
    const int* src = edge;
    const int* dst = edge + E;
    int nd = in_sizes[9];
    int ns = in_sizes[10];

    float* out   = (float*)d_out;
    float* out_x = out + (size_t)(nd + ns) * D256;

    float *px, *ph;
    __nv_bfloat16 *pxhi, *pxlo, *phhi, *phlo, *pmhi, *pmlo, *pbh, *pbl;
    cudaGetSymbolAddress((void**)&px, g_x);
    cudaGetSymbolAddress((void**)&ph, g_h);
    cudaGetSymbolAddress((void**)&pxhi, g_xhi);
    cudaGetSymbolAddress((void**)&pxlo, g_xlo);
    cudaGetSymbolAddress((void**)&phhi, g_hhi);
    cudaGetSymbolAddress((void**)&phlo, g_hlo);
    cudaGetSymbolAddress((void**)&pmhi, g_mhi);
    cudaGetSymbolAddress((void**)&pmlo, g_mlo);
    cudaGetSymbolAddress((void**)&pbh, g_Bhi);
    cudaGetSymbolAddress((void**)&pbl, g_Blo);

    static bool attr_set = false;
    if (!attr_set) {
        cudaFuncSetAttribute(gemm_mma_kernel,
                             cudaFuncAttributeMaxDynamicSharedMemorySize, SM_GEMM);
        attr_set = true;
    }

    int nb = (N + SCAN_BLK - 1) / SCAN_BLK;

    // --- CSR build + input gather + weight conversion ---
    zero_cnt_kernel<<<(N + 255) / 256, 256>>>(N);
    gather_x_kernel<<<(N * 32 + 255) / 256, 256>>>(emb, x_idx, N);
    convW_kernel<<<(2 * 256 * 512 + 255) / 256, 256>>>(W1l, W1r, W2l, W2r);
    hist_kernel<<<(E + 255) / 256, 256>>>(dst, E);
    scan_local_kernel<<<nb, SCAN_BLK>>>(N);
    scan_part_kernel<<<1, 1>>>(nb);
    scan_final_kernel<<<nb, SCAN_BLK>>>(N);
    scatter_kernel<<<(E + 255) / 256, 256>>>(src, dst, E);

    dim3 ggrid(2, (N + 127) / 128);

    // --- layer 1: agg(x fp32) -> mean hi/lo ; GEMM -> h fp32 + hi/lo ---
    aggregate_kernel<<<(N * 32 + 255) / 256, 256>>>(px, N);
    gemm_mma_kernel<<<ggrid, 256, SM_GEMM>>>(pmhi, pmlo, pxhi, pxlo, pbh, pbl,
                                             b1l, ph, phhi, phlo, N);

    // --- layer 2: agg(h fp32) -> mean hi/lo ; GEMM -> out_x fp32 ---
    aggregate_kernel<<<(N * 32 + 255) / 256, 256>>>(ph, N);
    gemm_mma_kernel<<<ggrid, 256, SM_GEMM>>>(pmhi, pmlo, phhi, phlo,
                                             pbh + 256 * 512, pbl + 256 * 512,
                                             b2l, out_x, nullptr, nullptr, N);

    // --- output gathers ---
    gather_out_kernel<<<nd + ns, 64>>>(out_x, drug, nd, se, out);
}